// round 13
// baseline (speedup 1.0000x reference)
#include <cuda_runtime.h>
#include <cuda_bf16.h>

#define N_NODES 50000
#define N_EDGES 800000
#define STEPS 10
#define NEG_SLOPE 0.01f
#define LN_EPS 1e-5f

#define SCAN_CHUNK 1024
#define N_CHUNKS ((N_NODES + SCAN_CHUNK - 1) / SCAN_CHUNK)   // 49

#define ENC_EDGE_BLOCKS 3125              // 3125*256 = 800000
#define ENC_NODE_BLOCKS 1184
#define E_TILE 128
#define N_TILES (N_EDGES / E_TILE)        // 6250 exact
#define EDGE_BLOCKS 1184
#define NODE_BLOCKS 592

// ---------------- device scratch (no allocation allowed) ----------------
__device__ __align__(16) float g_h  [N_NODES * 32];
__device__ __align__(16) float g_e  [N_EDGES * 32];     // receiver-sorted
__device__ __align__(16) float g_hs [N_NODES * 32];
__device__ __align__(16) float g_hd [N_NODES * 32];
__device__ __align__(16) float g_agg[N_NODES * 32];     // segment sums; consumer re-zeroes
__device__ float g_inv[N_NODES];
__device__ int   g_hist[N_NODES];         // zero-init; re-zeroed inside fused_encode each replay
__device__ int   g_off [N_NODES + 1];
__device__ int   g_cursor[N_NODES];
__device__ int   g_csum[N_CHUNKS];
__device__ __align__(16) int2 g_sr[N_EDGES];   // (sender, receiver) per sorted edge

__device__ __forceinline__ float leaky(float v) {
    return v >= 0.f ? v : NEG_SLOPE * v;
}

// ================= preprocessing =================
__global__ void hist_edges(const int* __restrict__ rcv) {
    int i = blockIdx.x * blockDim.x + threadIdx.x;
    if (i < N_EDGES) atomicAdd(&g_hist[rcv[i]], 1);
}

__global__ void scan_chunks() {
    __shared__ int sh[SCAN_CHUNK];
    int i = blockIdx.x * SCAN_CHUNK + threadIdx.x;
    int v = (i < N_NODES) ? g_hist[i] : 0;
    sh[threadIdx.x] = v;
    __syncthreads();
#pragma unroll
    for (int d = 1; d < SCAN_CHUNK; d <<= 1) {
        int t = (threadIdx.x >= d) ? sh[threadIdx.x - d] : 0;
        __syncthreads();
        sh[threadIdx.x] += t;
        __syncthreads();
    }
    if (i < N_NODES) g_off[i] = sh[threadIdx.x] - v;   // chunk-local exclusive
    if (threadIdx.x == SCAN_CHUNK - 1) g_csum[blockIdx.x] = sh[threadIdx.x];
}

__global__ void scan_sums() {
    int acc = 0;
    for (int c = 0; c < N_CHUNKS; c++) { int t = g_csum[c]; g_csum[c] = acc; acc += t; }
    g_off[N_NODES] = acc;
}

__global__ void add_offsets() {
    int i = blockIdx.x * blockDim.x + threadIdx.x;
    if (i < N_NODES) {
        int o = g_off[i] + g_csum[i / SCAN_CHUNK];
        g_off[i] = o;
        g_cursor[i] = o;
        g_inv[i] = 1.f / fmaxf((float)g_hist[i], 1.f);
    }
}

// ================= fused scatter + encoders + node_pre(step0) + agg zero =================
__global__ void __launch_bounds__(256) fused_encode(
        const float* __restrict__ ea, const int* __restrict__ snd, const int* __restrict__ rcv,
        const float* __restrict__ eeW, const float* __restrict__ eeb,
        const float* __restrict__ x, const float* __restrict__ neW, const float* __restrict__ neb,
        const float* __restrict__ eW0) {
    __shared__ float sw[64 * 32];
    __shared__ float sw2[224];

    if (blockIdx.x < ENC_EDGE_BLOCKS) {
        if (threadIdx.x < 96) sw[threadIdx.x] = eeW[threadIdx.x];
        else if (threadIdx.x < 128) sw[threadIdx.x] = eeb[threadIdx.x - 96];
        __syncthreads();
        int i = blockIdx.x * 256 + threadIdx.x;
        if (i < N_EDGES) {
            int r = rcv[i], s = snd[i];
            int pos = atomicAdd(&g_cursor[r], 1);
            g_sr[pos] = make_int2(s, r);
            float a0 = ea[i * 3 + 0], a1 = ea[i * 3 + 1], a2 = ea[i * 3 + 2];
            float4* dst = (float4*)&g_e[pos * 32];
#pragma unroll
            for (int c4 = 0; c4 < 8; c4++) {
                float4 v;
                v.x = leaky(sw[96 + c4 * 4 + 0] + a0 * sw[0 * 32 + c4 * 4 + 0] + a1 * sw[1 * 32 + c4 * 4 + 0] + a2 * sw[2 * 32 + c4 * 4 + 0]);
                v.y = leaky(sw[96 + c4 * 4 + 1] + a0 * sw[0 * 32 + c4 * 4 + 1] + a1 * sw[1 * 32 + c4 * 4 + 1] + a2 * sw[2 * 32 + c4 * 4 + 1]);
                v.z = leaky(sw[96 + c4 * 4 + 2] + a0 * sw[0 * 32 + c4 * 4 + 2] + a1 * sw[1 * 32 + c4 * 4 + 2] + a2 * sw[2 * 32 + c4 * 4 + 2]);
                v.w = leaky(sw[96 + c4 * 4 + 3] + a0 * sw[0 * 32 + c4 * 4 + 3] + a1 * sw[1 * 32 + c4 * 4 + 3] + a2 * sw[2 * 32 + c4 * 4 + 3]);
                dst[c4] = v;
            }
        }
    } else {
        for (int i = threadIdx.x; i < 2048; i += 256) sw[i] = eW0[32 * 32 + i];
        for (int i = threadIdx.x; i < 224; i += 256)
            sw2[i] = (i < 192) ? neW[i] : neb[i - 192];
        __syncthreads();
        int lane = threadIdx.x & 31;
        int nb = blockIdx.x - ENC_EDGE_BLOCKS;
        int warp = nb * 8 + (threadIdx.x >> 5);
        int nwarps = ENC_NODE_BLOCKS * 8;
        for (int n = warp; n < N_NODES; n += nwarps) {
            float a = sw2[192 + lane];
#pragma unroll
            for (int k = 0; k < 6; k++) a += x[n * 6 + k] * sw2[k * 32 + lane];
            float hv = leaky(a);
            g_h[n * 32 + lane] = hv;
            float aS = 0.f, aD = 0.f;
#pragma unroll
            for (int k = 0; k < 32; k++) {
                float t = __shfl_sync(0xffffffffu, hv, k);
                aS += t * sw[k * 32 + lane];
                aD += t * sw[(32 + k) * 32 + lane];
            }
            g_hs[n * 32 + lane] = aS;
            g_hd[n * 32 + lane] = aD;
            g_agg[n * 32 + lane] = 0.f;      // zero agg for step-0 edge_update
        }
        int gtid = nb * 256 + threadIdx.x;
        for (int i = gtid; i < N_NODES; i += ENC_NODE_BLOCKS * 256) g_hist[i] = 0;
    }
}

// ========== per-step: edge update — thread-per-edge, register LN, fused tile aggregation ====
__global__ void __launch_bounds__(128) edge_update(
        const float* __restrict__ eW, const float* __restrict__ eb,
        const float* __restrict__ lns, const float* __restrict__ lnb, int last) {
    __shared__ float  sW[32 * 32];        // W rows 0..31, row-major [k*32+c]
    __shared__ float4 sprm[24];           // bias[0:8), scale[8:16), shift[16:24) as float4
    __shared__ float  sE[E_TILE * 36];    // 128 edge rows, stride 36 (quarter-warp conflict-free)
    __shared__ int    sRcv[E_TILE];       // receiver id per tile row

    int tid = threadIdx.x;
    for (int i = tid; i < 1024; i += 128) sW[i] = eW[i];
    if (tid < 8)       sprm[tid] = *(const float4*)&eb [tid * 4];
    else if (tid < 16) sprm[tid] = *(const float4*)&lns[(tid - 8) * 4];
    else if (tid < 24) sprm[tid] = *(const float4*)&lnb[(tid - 16) * 4];
    __syncthreads();

    for (int tile = blockIdx.x; tile < N_TILES; tile += gridDim.x) {
        int base = tile * E_TILE;
        // ---- phase 1: coalesced load of 128 e-rows into smem ----
        for (int j = tid; j < E_TILE * 8; j += 128) {
            int row = j >> 3, c4 = j & 7;
            *(float4*)&sE[row * 36 + c4 * 4] = *(const float4*)&g_e[(base + row) * 32 + c4 * 4];
        }
        __syncthreads();

        // ---- phase 2: each thread fully owns edge base+tid ----
        {
            int e = base + tid;
            int2 sr = g_sr[e];
            sRcv[tid] = sr.y;
            float4 u[8];
#pragma unroll
            for (int c4 = 0; c4 < 8; c4++) u[c4] = *(const float4*)&sE[tid * 36 + c4 * 4];

            // m init = bias + hs[s] + hd[r]
            float4 m[8];
#pragma unroll
            for (int c4 = 0; c4 < 8; c4++) {
                float4 hs4 = *(const float4*)&g_hs[sr.x * 32 + c4 * 4];
                float4 hd4 = *(const float4*)&g_hd[sr.y * 32 + c4 * 4];
                float4 b4  = sprm[c4];
                m[c4].x = b4.x + hs4.x + hd4.x;
                m[c4].y = b4.y + hs4.y + hd4.y;
                m[c4].z = b4.z + hs4.z + hd4.z;
                m[c4].w = b4.w + hs4.w + hd4.w;
            }
            // GEMV: m_c += sum_k u_k * W[k][c]; W via warp-broadcast LDS.128
#pragma unroll
            for (int k4 = 0; k4 < 8; k4++) {
                float us[4] = {u[k4].x, u[k4].y, u[k4].z, u[k4].w};
#pragma unroll
                for (int kk = 0; kk < 4; kk++) {
                    const float* wr = &sW[(k4 * 4 + kk) * 32];
                    float s = us[kk];
#pragma unroll
                    for (int c4 = 0; c4 < 8; c4++) {
                        float4 w4 = *(const float4*)&wr[c4 * 4];
                        m[c4].x += s * w4.x;  m[c4].y += s * w4.y;
                        m[c4].z += s * w4.z;  m[c4].w += s * w4.w;
                    }
                }
            }
            // leaky + LN stats (pure register math — no shuffles)
            float4 s4 = make_float4(0.f, 0.f, 0.f, 0.f);
            float4 q4 = make_float4(0.f, 0.f, 0.f, 0.f);
#pragma unroll
            for (int c4 = 0; c4 < 8; c4++) {
                m[c4].x = leaky(m[c4].x);  m[c4].y = leaky(m[c4].y);
                m[c4].z = leaky(m[c4].z);  m[c4].w = leaky(m[c4].w);
                s4.x += m[c4].x;  s4.y += m[c4].y;  s4.z += m[c4].z;  s4.w += m[c4].w;
                q4.x = fmaf(m[c4].x, m[c4].x, q4.x);
                q4.y = fmaf(m[c4].y, m[c4].y, q4.y);
                q4.z = fmaf(m[c4].z, m[c4].z, q4.z);
                q4.w = fmaf(m[c4].w, m[c4].w, q4.w);
            }
            float sm = (s4.x + s4.y) + (s4.z + s4.w);
            float qq = (q4.x + q4.y) + (q4.z + q4.w);
            float mu  = sm * (1.f / 32.f);
            float var = fmaxf(qq * (1.f / 32.f) - mu * mu, 0.f);
            float rs  = rsqrtf(var + LN_EPS);
#pragma unroll
            for (int c4 = 0; c4 < 8; c4++) {
                float4 sc4 = sprm[8 + c4], bi4 = sprm[16 + c4];
                float4 en;
                en.x = u[c4].x + (m[c4].x - mu) * rs * sc4.x + bi4.x;
                en.y = u[c4].y + (m[c4].y - mu) * rs * sc4.y + bi4.y;
                en.z = u[c4].z + (m[c4].z - mu) * rs * sc4.z + bi4.z;
                en.w = u[c4].w + (m[c4].w - mu) * rs * sc4.w + bi4.w;
                *(float4*)&sE[tid * 36 + c4 * 4] = en;
            }
        }
        __syncthreads();

        // ---- phase 3: coalesced store (skip on last step — e is dead afterwards) ----
        if (!last) {
            for (int j = tid; j < E_TILE * 8; j += 128) {
                int row = j >> 3, c4 = j & 7;
                *(float4*)&g_e[(base + row) * 32 + c4 * 4] = *(const float4*)&sE[row * 36 + c4 * 4];
            }
        }

        // ---- phase 4: in-tile segmented aggregation -> g_agg ----
        // thread tid: column c = tid&31, sub-block sb = tid>>5 scans 32 rows.
        {
            int c  = tid & 31;
            int sb = tid >> 5;
            int cur = sRcv[sb * 32];     // broadcast LDS (same row for whole warp)
            float run = 0.f;
#pragma unroll 4
            for (int i = 0; i < 32; i++) {
                int row = sb * 32 + i;
                int r = sRcv[row];       // broadcast
                float v = sE[row * 36 + c];   // conflict-free
                if (r != cur) {
                    atomicAdd(&g_agg[cur * 32 + c], run);   // coalesced across warp
                    run = 0.f;
                    cur = r;
                }
                run += v;
            }
            atomicAdd(&g_agg[cur * 32 + c], run);
        }
        __syncthreads();
    }
}

// ================= per-step: node update (agg precomputed) + next-step Hs/Hd or decoder ====
__global__ void __launch_bounds__(256) node_update(
        const float* __restrict__ nW, const float* __restrict__ nb,
        const float* __restrict__ lns, const float* __restrict__ lnb,
        const float* __restrict__ eW_next, int last,
        const float* __restrict__ dW1, const float* __restrict__ db1,
        const float* __restrict__ dW2, const float* __restrict__ db2,
        float* __restrict__ out) {
    __shared__ float wsT [32 * 68];   // node W transposed: wsT[c*68 + k], k in [0,64)
    __shared__ float ws2T[32 * 68];   // next-step eW rows 32..95 transposed (or dec_W1)
    __shared__ float sv  [8 * 64];    // per-warp staging: [0:32) av, [32:64) hn
    __shared__ float prm [96];

    for (int i = threadIdx.x; i < 2048; i += 256) {
        int k = i >> 5, c = i & 31;
        wsT[c * 68 + k] = nW[i];
        if (last) { if (i < 1024) ws2T[c * 68 + k] = dW1[i]; }
        else        ws2T[c * 68 + k] = eW_next[32 * 32 + i];
    }
    if (threadIdx.x < 32) {
        prm[threadIdx.x]      = nb[threadIdx.x];
        prm[32 + threadIdx.x] = lns[threadIdx.x];
        prm[64 + threadIdx.x] = lnb[threadIdx.x];
    }
    __syncthreads();
    int lane = threadIdx.x & 31;
    int wslot = (threadIdx.x >> 5) * 64;
    int warp = (blockIdx.x * blockDim.x + threadIdx.x) >> 5;
    int nwarps = (gridDim.x * blockDim.x) >> 5;
    float bias = prm[lane], sc = prm[32 + lane], bi = prm[64 + lane];

    for (int n = warp; n < N_NODES; n += nwarps) {
        float av = g_agg[n * 32 + lane] * g_inv[n];
        g_agg[n * 32 + lane] = 0.f;          // ready for next step's edge_update
        float hv = g_h[n * 32 + lane];       // brings row into L1
        sv[wslot + lane] = av;
        __syncwarp();

        float acc = bias, acb = 0.f;
#pragma unroll
        for (int k4 = 0; k4 < 8; k4++) {
            float4 hb = *(const float4*)&g_h[n * 32 + k4 * 4];   // uniform broadcast, L1-hit
            float4 ab = *(const float4*)&sv[wslot + k4 * 4];     // broadcast LDS.128
            const float* wr = &wsT[lane * 68 + k4 * 4];
            float4 w1 = *(const float4*)wr;
            float4 w2 = *(const float4*)(wr + 32);
            acc += hb.x * w1.x + ab.x * w2.x;
            acb += hb.y * w1.y + ab.y * w2.y;
            acc += hb.z * w1.z + ab.z * w2.z;
            acb += hb.w * w1.w + ab.w * w2.w;
        }
        float m = leaky(acc + acb);
        float sm = m, qq = m * m;
#pragma unroll
        for (int d = 16; d; d >>= 1) {
            sm += __shfl_xor_sync(0xffffffffu, sm, d);
            qq += __shfl_xor_sync(0xffffffffu, qq, d);
        }
        float mu = sm * (1.f / 32.f);
        float var = fmaxf(qq * (1.f / 32.f) - mu * mu, 0.f);
        float hn = hv + (m - mu) * rsqrtf(var + LN_EPS) * sc + bi;
        g_h[n * 32 + lane] = hn;
        sv[wslot + 32 + lane] = hn;
        __syncwarp();

        if (!last) {
            float aS = 0.f, aD = 0.f;
#pragma unroll
            for (int k4 = 0; k4 < 8; k4++) {
                float4 hb = *(const float4*)&sv[wslot + 32 + k4 * 4];
                const float* wr = &ws2T[lane * 68 + k4 * 4];
                float4 w1 = *(const float4*)wr;
                float4 w2 = *(const float4*)(wr + 32);
                aS += hb.x * w1.x; aD += hb.x * w2.x;
                aS += hb.y * w1.y; aD += hb.y * w2.y;
                aS += hb.z * w1.z; aD += hb.z * w2.z;
                aS += hb.w * w1.w; aD += hb.w * w2.w;
            }
            g_hs[n * 32 + lane] = aS;
            g_hd[n * 32 + lane] = aD;
        } else {
            float t = db1[lane];
#pragma unroll
            for (int k4 = 0; k4 < 8; k4++) {
                float4 hb = *(const float4*)&sv[wslot + 32 + k4 * 4];
                float4 w1 = *(const float4*)&ws2T[lane * 68 + k4 * 4];
                t += hb.x * w1.x + hb.y * w1.y + hb.z * w1.z + hb.w * w1.w;
            }
            t = leaky(t) * dW2[lane];
#pragma unroll
            for (int d = 16; d; d >>= 1)
                t += __shfl_xor_sync(0xffffffffu, t, d);
            if (lane == 0) out[n] = t + db2[0];
        }
        __syncwarp();
    }
}

// ================= launch =================
extern "C" void kernel_launch(void* const* d_in, const int* in_sizes, int n_in,
                              void* d_out, int out_size) {
    const float* x   = (const float*)d_in[0];
    const float* ea  = (const float*)d_in[1];
    const int*   snd = (const int*)d_in[2];
    const int*   rcv = (const int*)d_in[3];
    const float* neW = (const float*)d_in[4];
    const float* neb = (const float*)d_in[5];
    const float* eeW = (const float*)d_in[6];
    const float* eeb = (const float*)d_in[7];
    const float* eW  = (const float*)d_in[8];
    const float* eb  = (const float*)d_in[9];
    const float* els = (const float*)d_in[10];
    const float* elb = (const float*)d_in[11];
    const float* nW  = (const float*)d_in[12];
    const float* nb  = (const float*)d_in[13];
    const float* nls = (const float*)d_in[14];
    const float* nlb = (const float*)d_in[15];
    const float* dW1 = (const float*)d_in[16];
    const float* db1 = (const float*)d_in[17];
    const float* dW2 = (const float*)d_in[18];
    const float* db2 = (const float*)d_in[19];
    float* out = (float*)d_out;

    hist_edges<<<(N_EDGES + 255) / 256, 256>>>(rcv);
    scan_chunks<<<N_CHUNKS, SCAN_CHUNK>>>();
    scan_sums<<<1, 1>>>();
    add_offsets<<<(N_NODES + 255) / 256, 256>>>();
    fused_encode<<<ENC_EDGE_BLOCKS + ENC_NODE_BLOCKS, 256>>>(
        ea, snd, rcv, eeW, eeb, x, neW, neb, eW);

    for (int s = 0; s < STEPS; s++) {
        int last = (s == STEPS - 1);
        edge_update<<<EDGE_BLOCKS, 128>>>(eW + s * 96 * 32, eb + s * 32,
                                          els + s * 32, elb + s * 32, last);
        node_update<<<NODE_BLOCKS, 256>>>(nW + s * 64 * 32, nb + s * 32,
                                          nls + s * 32, nlb + s * 32,
                                          eW + (s + 1 < STEPS ? (s + 1) * 96 * 32 : 0), last,
                                          dW1, db1, dW2, db2, out);
    }
}

// round 14
// speedup vs baseline: 1.6547x; 1.6547x over previous
#include <cuda_runtime.h>
#include <cuda_bf16.h>

#define N_NODES 50000
#define N_EDGES 800000
#define STEPS 10
#define NEG_SLOPE 0.01f
#define LN_EPS 1e-5f

#define SCAN_CHUNK 1024
#define N_CHUNKS ((N_NODES + SCAN_CHUNK - 1) / SCAN_CHUNK)   // 49

#define ENC_EDGE_BLOCKS 3125              // 3125*256 = 800000
#define ENC_NODE_BLOCKS 1184
#define E_TILE 128
#define N_TILES (N_EDGES / E_TILE)        // 6250 exact
#define EDGE_BLOCKS 1184
#define NODE_BLOCKS 592

// ---------------- device scratch (no allocation allowed) ----------------
__device__ __align__(16) float g_h  [N_NODES * 32];
__device__ __align__(16) float g_e  [N_EDGES * 32];     // receiver-sorted
__device__ __align__(16) float g_hs [N_NODES * 32];
__device__ __align__(16) float g_hd [N_NODES * 32];
__device__ float g_inv[N_NODES];
__device__ int   g_hist[N_NODES];         // zero-init; re-zeroed inside fused_encode each replay
__device__ int   g_off [N_NODES + 1];
__device__ int   g_cursor[N_NODES];
__device__ int   g_csum[N_CHUNKS];
__device__ __align__(16) int2 g_sr[N_EDGES];   // (sender, receiver) per sorted edge

__device__ __forceinline__ float leaky(float v) {
    return v >= 0.f ? v : NEG_SLOPE * v;
}

// ================= preprocessing =================
__global__ void hist_edges(const int* __restrict__ rcv) {
    int i = blockIdx.x * blockDim.x + threadIdx.x;
    if (i < N_EDGES) atomicAdd(&g_hist[rcv[i]], 1);
}

__global__ void scan_chunks() {
    __shared__ int sh[SCAN_CHUNK];
    int i = blockIdx.x * SCAN_CHUNK + threadIdx.x;
    int v = (i < N_NODES) ? g_hist[i] : 0;
    sh[threadIdx.x] = v;
    __syncthreads();
#pragma unroll
    for (int d = 1; d < SCAN_CHUNK; d <<= 1) {
        int t = (threadIdx.x >= d) ? sh[threadIdx.x - d] : 0;
        __syncthreads();
        sh[threadIdx.x] += t;
        __syncthreads();
    }
    if (i < N_NODES) g_off[i] = sh[threadIdx.x] - v;   // chunk-local exclusive
    if (threadIdx.x == SCAN_CHUNK - 1) g_csum[blockIdx.x] = sh[threadIdx.x];
}

// 64-thread inclusive-scan of the 49 chunk sums (replaces serial 1-thread loop)
__global__ void scan_sums() {
    __shared__ int sh[64];
    int tid = threadIdx.x;
    int v = (tid < N_CHUNKS) ? g_csum[tid] : 0;
    sh[tid] = v;
    __syncthreads();
#pragma unroll
    for (int d = 1; d < 64; d <<= 1) {
        int t = (tid >= d) ? sh[tid - d] : 0;
        __syncthreads();
        sh[tid] += t;
        __syncthreads();
    }
    if (tid < N_CHUNKS) g_csum[tid] = sh[tid] - v;     // exclusive
    if (tid == 63) g_off[N_NODES] = sh[63];            // == N_EDGES
}

__global__ void add_offsets() {
    int i = blockIdx.x * blockDim.x + threadIdx.x;
    if (i < N_NODES) {
        int o = g_off[i] + g_csum[i / SCAN_CHUNK];
        g_off[i] = o;
        g_cursor[i] = o;
        g_inv[i] = 1.f / fmaxf((float)g_hist[i], 1.f);
    }
}

// ================= fused scatter + encoders + node_pre(step0) =================
__global__ void __launch_bounds__(256) fused_encode(
        const float* __restrict__ ea, const int* __restrict__ snd, const int* __restrict__ rcv,
        const float* __restrict__ eeW, const float* __restrict__ eeb,
        const float* __restrict__ x, const float* __restrict__ neW, const float* __restrict__ neb,
        const float* __restrict__ eW0) {
    __shared__ float sw[64 * 32];
    __shared__ float sw2[224];

    if (blockIdx.x < ENC_EDGE_BLOCKS) {
        if (threadIdx.x < 96) sw[threadIdx.x] = eeW[threadIdx.x];
        else if (threadIdx.x < 128) sw[threadIdx.x] = eeb[threadIdx.x - 96];
        __syncthreads();
        int i = blockIdx.x * 256 + threadIdx.x;
        if (i < N_EDGES) {
            int r = rcv[i], s = snd[i];
            int pos = atomicAdd(&g_cursor[r], 1);
            g_sr[pos] = make_int2(s, r);
            float a0 = ea[i * 3 + 0], a1 = ea[i * 3 + 1], a2 = ea[i * 3 + 2];
            float4* dst = (float4*)&g_e[pos * 32];
#pragma unroll
            for (int c4 = 0; c4 < 8; c4++) {
                float4 v;
                v.x = leaky(sw[96 + c4 * 4 + 0] + a0 * sw[0 * 32 + c4 * 4 + 0] + a1 * sw[1 * 32 + c4 * 4 + 0] + a2 * sw[2 * 32 + c4 * 4 + 0]);
                v.y = leaky(sw[96 + c4 * 4 + 1] + a0 * sw[0 * 32 + c4 * 4 + 1] + a1 * sw[1 * 32 + c4 * 4 + 1] + a2 * sw[2 * 32 + c4 * 4 + 1]);
                v.z = leaky(sw[96 + c4 * 4 + 2] + a0 * sw[0 * 32 + c4 * 4 + 2] + a1 * sw[1 * 32 + c4 * 4 + 2] + a2 * sw[2 * 32 + c4 * 4 + 2]);
                v.w = leaky(sw[96 + c4 * 4 + 3] + a0 * sw[0 * 32 + c4 * 4 + 3] + a1 * sw[1 * 32 + c4 * 4 + 3] + a2 * sw[2 * 32 + c4 * 4 + 3]);
                dst[c4] = v;
            }
        }
    } else {
        for (int i = threadIdx.x; i < 2048; i += 256) sw[i] = eW0[32 * 32 + i];
        for (int i = threadIdx.x; i < 224; i += 256)
            sw2[i] = (i < 192) ? neW[i] : neb[i - 192];
        __syncthreads();
        int lane = threadIdx.x & 31;
        int nb = blockIdx.x - ENC_EDGE_BLOCKS;
        int warp = nb * 8 + (threadIdx.x >> 5);
        int nwarps = ENC_NODE_BLOCKS * 8;
        for (int n = warp; n < N_NODES; n += nwarps) {
            float a = sw2[192 + lane];
#pragma unroll
            for (int k = 0; k < 6; k++) a += x[n * 6 + k] * sw2[k * 32 + lane];
            float hv = leaky(a);
            g_h[n * 32 + lane] = hv;
            float aS = 0.f, aD = 0.f;
#pragma unroll
            for (int k = 0; k < 32; k++) {
                float t = __shfl_sync(0xffffffffu, hv, k);
                aS += t * sw[k * 32 + lane];
                aD += t * sw[(32 + k) * 32 + lane];
            }
            g_hs[n * 32 + lane] = aS;
            g_hd[n * 32 + lane] = aD;
        }
        int gtid = nb * 256 + threadIdx.x;
        for (int i = gtid; i < N_NODES; i += ENC_NODE_BLOCKS * 256) g_hist[i] = 0;
    }
}

// ================= per-step: edge update — THREAD-PER-EDGE, register LN =================
__global__ void __launch_bounds__(128) edge_update(
        const float* __restrict__ eW, const float* __restrict__ eb,
        const float* __restrict__ lns, const float* __restrict__ lnb, int last) {
    __shared__ float  sW[32 * 32];        // W rows 0..31, row-major [k*32+c]
    __shared__ float4 sprm[24];           // bias[0:8), scale[8:16), shift[16:24) as float4
    __shared__ float  sE[E_TILE * 36];    // 128 edge rows, stride 36 (quarter-warp conflict-free)

    int tid = threadIdx.x;
    for (int i = tid; i < 1024; i += 128) sW[i] = eW[i];
    if (tid < 8)       sprm[tid] = *(const float4*)&eb [tid * 4];
    else if (tid < 16) sprm[tid] = *(const float4*)&lns[(tid - 8) * 4];
    else if (tid < 24) sprm[tid] = *(const float4*)&lnb[(tid - 16) * 4];
    __syncthreads();

    for (int tile = blockIdx.x; tile < N_TILES; tile += gridDim.x) {
        int base = tile * E_TILE;
        // ---- phase 1: coalesced load of 128 e-rows into smem ----
        for (int j = tid; j < E_TILE * 8; j += 128) {
            int row = j >> 3, c4 = j & 7;
            *(float4*)&sE[row * 36 + c4 * 4] = *(const float4*)&g_e[(base + row) * 32 + c4 * 4];
        }
        __syncthreads();

        // ---- phase 2: each thread fully owns edge base+tid ----
        {
            int e = base + tid;
            int2 sr = g_sr[e];
            float4 u[8];
#pragma unroll
            for (int c4 = 0; c4 < 8; c4++) u[c4] = *(const float4*)&sE[tid * 36 + c4 * 4];

            // m init = bias + hs[s] + hd[r]  (gathers overlap with GEMV below via OOO sched)
            float4 m[8];
#pragma unroll
            for (int c4 = 0; c4 < 8; c4++) {
                float4 hs4 = *(const float4*)&g_hs[sr.x * 32 + c4 * 4];
                float4 hd4 = *(const float4*)&g_hd[sr.y * 32 + c4 * 4];
                float4 b4  = sprm[c4];
                m[c4].x = b4.x + hs4.x + hd4.x;
                m[c4].y = b4.y + hs4.y + hd4.y;
                m[c4].z = b4.z + hs4.z + hd4.z;
                m[c4].w = b4.w + hs4.w + hd4.w;
            }
            // GEMV: m_c += sum_k u_k * W[k][c]; W via warp-broadcast LDS.128
#pragma unroll
            for (int k4 = 0; k4 < 8; k4++) {
                float us[4] = {u[k4].x, u[k4].y, u[k4].z, u[k4].w};
#pragma unroll
                for (int kk = 0; kk < 4; kk++) {
                    const float* wr = &sW[(k4 * 4 + kk) * 32];
                    float s = us[kk];
#pragma unroll
                    for (int c4 = 0; c4 < 8; c4++) {
                        float4 w4 = *(const float4*)&wr[c4 * 4];
                        m[c4].x += s * w4.x;  m[c4].y += s * w4.y;
                        m[c4].z += s * w4.z;  m[c4].w += s * w4.w;
                    }
                }
            }
            // leaky + LN stats (pure register math — no shuffles)
            float4 s4 = make_float4(0.f, 0.f, 0.f, 0.f);
            float4 q4 = make_float4(0.f, 0.f, 0.f, 0.f);
#pragma unroll
            for (int c4 = 0; c4 < 8; c4++) {
                m[c4].x = leaky(m[c4].x);  m[c4].y = leaky(m[c4].y);
                m[c4].z = leaky(m[c4].z);  m[c4].w = leaky(m[c4].w);
                s4.x += m[c4].x;  s4.y += m[c4].y;  s4.z += m[c4].z;  s4.w += m[c4].w;
                q4.x = fmaf(m[c4].x, m[c4].x, q4.x);
                q4.y = fmaf(m[c4].y, m[c4].y, q4.y);
                q4.z = fmaf(m[c4].z, m[c4].z, q4.z);
                q4.w = fmaf(m[c4].w, m[c4].w, q4.w);
            }
            float sm = (s4.x + s4.y) + (s4.z + s4.w);
            float qq = (q4.x + q4.y) + (q4.z + q4.w);
            float mu  = sm * (1.f / 32.f);
            float var = fmaxf(qq * (1.f / 32.f) - mu * mu, 0.f);
            float rs  = rsqrtf(var + LN_EPS);
            // y = (m-mu)*rs*scale + shift; en = u + y; write back to smem slot
#pragma unroll
            for (int c4 = 0; c4 < 8; c4++) {
                float4 sc4 = sprm[8 + c4], bi4 = sprm[16 + c4];
                float4 en;
                en.x = u[c4].x + (m[c4].x - mu) * rs * sc4.x + bi4.x;
                en.y = u[c4].y + (m[c4].y - mu) * rs * sc4.y + bi4.y;
                en.z = u[c4].z + (m[c4].z - mu) * rs * sc4.z + bi4.z;
                en.w = u[c4].w + (m[c4].w - mu) * rs * sc4.w + bi4.w;
                *(float4*)&sE[tid * 36 + c4 * 4] = en;
            }
        }
        __syncthreads();

        // ---- phase 3: coalesced store (the last step's aggregation happens in node_update,
        //      which still reads g_e — so only skip when truly dead; here e IS still read
        //      by node_update's CSR gather, so skip ONLY the final step where... it is read.
        //      Correction: node_update reads g_e every step, including the last. Store always.
        //      `last` currently unused for the store; kept for launch signature stability.
        for (int j = tid; j < E_TILE * 8; j += 128) {
            int row = j >> 3, c4 = j & 7;
            *(float4*)&g_e[(base + row) * 32 + c4 * 4] = *(const float4*)&sE[row * 36 + c4 * 4];
        }
        __syncthreads();
    }
}

// ================= per-step: node update (CSR gather) + next-step Hs/Hd or decoder ====
__global__ void __launch_bounds__(256) node_update(
        const float* __restrict__ nW, const float* __restrict__ nb,
        const float* __restrict__ lns, const float* __restrict__ lnb,
        const float* __restrict__ eW_next, int last,
        const float* __restrict__ dW1, const float* __restrict__ db1,
        const float* __restrict__ dW2, const float* __restrict__ db2,
        float* __restrict__ out) {
    __shared__ float wsT [32 * 68];   // node W transposed: wsT[c*68 + k], k in [0,64)
    __shared__ float ws2T[32 * 68];   // next-step eW rows 32..95 transposed (or dec_W1)
    __shared__ float sv  [8 * 64];    // per-warp staging: [0:32) av, [32:64) hn
    __shared__ float prm [96];

    for (int i = threadIdx.x; i < 2048; i += 256) {
        int k = i >> 5, c = i & 31;
        wsT[c * 68 + k] = nW[i];
        if (last) { if (i < 1024) ws2T[c * 68 + k] = dW1[i]; }
        else        ws2T[c * 68 + k] = eW_next[32 * 32 + i];
    }
    if (threadIdx.x < 32) {
        prm[threadIdx.x]      = nb[threadIdx.x];
        prm[32 + threadIdx.x] = lns[threadIdx.x];
        prm[64 + threadIdx.x] = lnb[threadIdx.x];
    }
    __syncthreads();
    int lane = threadIdx.x & 31;
    int wslot = (threadIdx.x >> 5) * 64;
    int warp = (blockIdx.x * blockDim.x + threadIdx.x) >> 5;
    int nwarps = (gridDim.x * blockDim.x) >> 5;
    float bias = prm[lane], sc = prm[32 + lane], bi = prm[64 + lane];

    for (int n = warp; n < N_NODES; n += nwarps) {
        int beg = g_off[n], end = g_off[n + 1];
        float s0 = 0.f, s1 = 0.f, s2 = 0.f, s3 = 0.f;
        int j = beg;
        for (; j + 3 < end; j += 4) {
            s0 += g_e[(j + 0) * 32 + lane];
            s1 += g_e[(j + 1) * 32 + lane];
            s2 += g_e[(j + 2) * 32 + lane];
            s3 += g_e[(j + 3) * 32 + lane];
        }
        for (; j < end; j++) s0 += g_e[j * 32 + lane];
        float av = ((s0 + s1) + (s2 + s3)) * g_inv[n];
        float hv = g_h[n * 32 + lane];       // brings row into L1
        sv[wslot + lane] = av;
        __syncwarp();

        float acc = bias, acb = 0.f;
#pragma unroll
        for (int k4 = 0; k4 < 8; k4++) {
            float4 hb = *(const float4*)&g_h[n * 32 + k4 * 4];   // uniform broadcast, L1-hit
            float4 ab = *(const float4*)&sv[wslot + k4 * 4];     // broadcast LDS.128
            const float* wr = &wsT[lane * 68 + k4 * 4];
            float4 w1 = *(const float4*)wr;
            float4 w2 = *(const float4*)(wr + 32);
            acc += hb.x * w1.x + ab.x * w2.x;
            acb += hb.y * w1.y + ab.y * w2.y;
            acc += hb.z * w1.z + ab.z * w2.z;
            acb += hb.w * w1.w + ab.w * w2.w;
        }
        float m = leaky(acc + acb);
        float sm = m, qq = m * m;
#pragma unroll
        for (int d = 16; d; d >>= 1) {
            sm += __shfl_xor_sync(0xffffffffu, sm, d);
            qq += __shfl_xor_sync(0xffffffffu, qq, d);
        }
        float mu = sm * (1.f / 32.f);
        float var = fmaxf(qq * (1.f / 32.f) - mu * mu, 0.f);
        float hn = hv + (m - mu) * rsqrtf(var + LN_EPS) * sc + bi;
        g_h[n * 32 + lane] = hn;
        sv[wslot + 32 + lane] = hn;
        __syncwarp();

        if (!last) {
            float aS = 0.f, aD = 0.f;
#pragma unroll
            for (int k4 = 0; k4 < 8; k4++) {
                float4 hb = *(const float4*)&sv[wslot + 32 + k4 * 4];
                const float* wr = &ws2T[lane * 68 + k4 * 4];
                float4 w1 = *(const float4*)wr;
                float4 w2 = *(const float4*)(wr + 32);
                aS += hb.x * w1.x; aD += hb.x * w2.x;
                aS += hb.y * w1.y; aD += hb.y * w2.y;
                aS += hb.z * w1.z; aD += hb.z * w2.z;
                aS += hb.w * w1.w; aD += hb.w * w2.w;
            }
            g_hs[n * 32 + lane] = aS;
            g_hd[n * 32 + lane] = aD;
        } else {
            float t = db1[lane];
#pragma unroll
            for (int k4 = 0; k4 < 8; k4++) {
                float4 hb = *(const float4*)&sv[wslot + 32 + k4 * 4];
                float4 w1 = *(const float4*)&ws2T[lane * 68 + k4 * 4];
                t += hb.x * w1.x + hb.y * w1.y + hb.z * w1.z + hb.w * w1.w;
            }
            t = leaky(t) * dW2[lane];
#pragma unroll
            for (int d = 16; d; d >>= 1)
                t += __shfl_xor_sync(0xffffffffu, t, d);
            if (lane == 0) out[n] = t + db2[0];
        }
        __syncwarp();
    }
}

// ================= launch =================
extern "C" void kernel_launch(void* const* d_in, const int* in_sizes, int n_in,
                              void* d_out, int out_size) {
    const float* x   = (const float*)d_in[0];
    const float* ea  = (const float*)d_in[1];
    const int*   snd = (const int*)d_in[2];
    const int*   rcv = (const int*)d_in[3];
    const float* neW = (const float*)d_in[4];
    const float* neb = (const float*)d_in[5];
    const float* eeW = (const float*)d_in[6];
    const float* eeb = (const float*)d_in[7];
    const float* eW  = (const float*)d_in[8];
    const float* eb  = (const float*)d_in[9];
    const float* els = (const float*)d_in[10];
    const float* elb = (const float*)d_in[11];
    const float* nW  = (const float*)d_in[12];
    const float* nb  = (const float*)d_in[13];
    const float* nls = (const float*)d_in[14];
    const float* nlb = (const float*)d_in[15];
    const float* dW1 = (const float*)d_in[16];
    const float* db1 = (const float*)d_in[17];
    const float* dW2 = (const float*)d_in[18];
    const float* db2 = (const float*)d_in[19];
    float* out = (float*)d_out;

    hist_edges<<<(N_EDGES + 255) / 256, 256>>>(rcv);
    scan_chunks<<<N_CHUNKS, SCAN_CHUNK>>>();
    scan_sums<<<1, 64>>>();
    add_offsets<<<(N_NODES + 255) / 256, 256>>>();
    fused_encode<<<ENC_EDGE_BLOCKS + ENC_NODE_BLOCKS, 256>>>(
        ea, snd, rcv, eeW, eeb, x, neW, neb, eW);

    for (int s = 0; s < STEPS; s++) {
        int last = (s == STEPS - 1);
        edge_update<<<EDGE_BLOCKS, 128>>>(eW + s * 96 * 32, eb + s * 32,
                                          els + s * 32, elb + s * 32, last);
        node_update<<<NODE_BLOCKS, 256>>>(nW + s * 64 * 32, nb + s * 32,
                                          nls + s * 32, nlb + s * 32,
                                          eW + (s + 1 < STEPS ? (s + 1) * 96 * 32 : 0), last,
                                          dW1, db1, dW2, db2, out);
    }
}

// round 15
// speedup vs baseline: 1.7165x; 1.0373x over previous
#include <cuda_runtime.h>
#include <cuda_bf16.h>

#define N_NODES 50000
#define N_EDGES 800000
#define STEPS 10
#define NEG_SLOPE 0.01f
#define LN_EPS 1e-5f

#define SCAN_CHUNK 1024
#define N_CHUNKS ((N_NODES + SCAN_CHUNK - 1) / SCAN_CHUNK)   // 49

#define ENC_EDGE_BLOCKS 3125              // 3125*256 = 800000
#define ENC_NODE_BLOCKS 1184
#define E_TILE 128
#define N_TILES (N_EDGES / E_TILE)        // 6250 exact
#define EDGE_BLOCKS 1184
#define NODE_BLOCKS 592

// ---------------- device scratch (no allocation allowed) ----------------
__device__ __align__(16) float g_h  [N_NODES * 32];
__device__ __align__(16) float g_e  [N_EDGES * 32];     // receiver-sorted
__device__ __align__(16) float g_hs [N_NODES * 32];
__device__ __align__(16) float g_hd [N_NODES * 32];
__device__ float g_inv[N_NODES];
__device__ int   g_hist[N_NODES];         // zero-init; re-zeroed inside fused_encode each replay
__device__ int   g_off [N_NODES + 1];
__device__ int   g_cursor[N_NODES];
__device__ int   g_csum[N_CHUNKS];
__device__ __align__(16) int2 g_sr[N_EDGES];   // (sender, receiver) per sorted edge

__device__ __forceinline__ float leaky(float v) {
    return v >= 0.f ? v : NEG_SLOPE * v;
}

// ================= preprocessing =================
__global__ void hist_edges(const int* __restrict__ rcv) {
    int i = blockIdx.x * blockDim.x + threadIdx.x;
    if (i < N_EDGES) atomicAdd(&g_hist[rcv[i]], 1);
}

__global__ void scan_chunks() {
    __shared__ int sh[SCAN_CHUNK];
    int i = blockIdx.x * SCAN_CHUNK + threadIdx.x;
    int v = (i < N_NODES) ? g_hist[i] : 0;
    sh[threadIdx.x] = v;
    __syncthreads();
#pragma unroll
    for (int d = 1; d < SCAN_CHUNK; d <<= 1) {
        int t = (threadIdx.x >= d) ? sh[threadIdx.x - d] : 0;
        __syncthreads();
        sh[threadIdx.x] += t;
        __syncthreads();
    }
    if (i < N_NODES) g_off[i] = sh[threadIdx.x] - v;   // chunk-local exclusive
    if (threadIdx.x == SCAN_CHUNK - 1) g_csum[blockIdx.x] = sh[threadIdx.x];
}

// 64-thread inclusive-scan of the 49 chunk sums
__global__ void scan_sums() {
    __shared__ int sh[64];
    int tid = threadIdx.x;
    int v = (tid < N_CHUNKS) ? g_csum[tid] : 0;
    sh[tid] = v;
    __syncthreads();
#pragma unroll
    for (int d = 1; d < 64; d <<= 1) {
        int t = (tid >= d) ? sh[tid - d] : 0;
        __syncthreads();
        sh[tid] += t;
        __syncthreads();
    }
    if (tid < N_CHUNKS) g_csum[tid] = sh[tid] - v;     // exclusive
    if (tid == 63) g_off[N_NODES] = sh[63];            // == N_EDGES
}

__global__ void add_offsets() {
    int i = blockIdx.x * blockDim.x + threadIdx.x;
    if (i < N_NODES) {
        int o = g_off[i] + g_csum[i / SCAN_CHUNK];
        g_off[i] = o;
        g_cursor[i] = o;
        g_inv[i] = 1.f / fmaxf((float)g_hist[i], 1.f);
    }
}

// ================= fused scatter + encoders + node_pre(step0) =================
__global__ void __launch_bounds__(256) fused_encode(
        const float* __restrict__ ea, const int* __restrict__ snd, const int* __restrict__ rcv,
        const float* __restrict__ eeW, const float* __restrict__ eeb,
        const float* __restrict__ x, const float* __restrict__ neW, const float* __restrict__ neb,
        const float* __restrict__ eW0) {
    __shared__ float sw[64 * 32];
    __shared__ float sw2[224];

    if (blockIdx.x < ENC_EDGE_BLOCKS) {
        if (threadIdx.x < 96) sw[threadIdx.x] = eeW[threadIdx.x];
        else if (threadIdx.x < 128) sw[threadIdx.x] = eeb[threadIdx.x - 96];
        __syncthreads();
        int i = blockIdx.x * 256 + threadIdx.x;
        if (i < N_EDGES) {
            int r = rcv[i], s = snd[i];
            int pos = atomicAdd(&g_cursor[r], 1);
            g_sr[pos] = make_int2(s, r);
            float a0 = ea[i * 3 + 0], a1 = ea[i * 3 + 1], a2 = ea[i * 3 + 2];
            float4* dst = (float4*)&g_e[pos * 32];
#pragma unroll
            for (int c4 = 0; c4 < 8; c4++) {
                float4 v;
                v.x = leaky(sw[96 + c4 * 4 + 0] + a0 * sw[0 * 32 + c4 * 4 + 0] + a1 * sw[1 * 32 + c4 * 4 + 0] + a2 * sw[2 * 32 + c4 * 4 + 0]);
                v.y = leaky(sw[96 + c4 * 4 + 1] + a0 * sw[0 * 32 + c4 * 4 + 1] + a1 * sw[1 * 32 + c4 * 4 + 1] + a2 * sw[2 * 32 + c4 * 4 + 1]);
                v.z = leaky(sw[96 + c4 * 4 + 2] + a0 * sw[0 * 32 + c4 * 4 + 2] + a1 * sw[1 * 32 + c4 * 4 + 2] + a2 * sw[2 * 32 + c4 * 4 + 2]);
                v.w = leaky(sw[96 + c4 * 4 + 3] + a0 * sw[0 * 32 + c4 * 4 + 3] + a1 * sw[1 * 32 + c4 * 4 + 3] + a2 * sw[2 * 32 + c4 * 4 + 3]);
                dst[c4] = v;
            }
        }
    } else {
        for (int i = threadIdx.x; i < 2048; i += 256) sw[i] = eW0[32 * 32 + i];
        for (int i = threadIdx.x; i < 224; i += 256)
            sw2[i] = (i < 192) ? neW[i] : neb[i - 192];
        __syncthreads();
        int lane = threadIdx.x & 31;
        int nb = blockIdx.x - ENC_EDGE_BLOCKS;
        int warp = nb * 8 + (threadIdx.x >> 5);
        int nwarps = ENC_NODE_BLOCKS * 8;
        for (int n = warp; n < N_NODES; n += nwarps) {
            float a = sw2[192 + lane];
#pragma unroll
            for (int k = 0; k < 6; k++) a += x[n * 6 + k] * sw2[k * 32 + lane];
            float hv = leaky(a);
            g_h[n * 32 + lane] = hv;
            float aS = 0.f, aD = 0.f;
#pragma unroll
            for (int k = 0; k < 32; k++) {
                float t = __shfl_sync(0xffffffffu, hv, k);
                aS += t * sw[k * 32 + lane];
                aD += t * sw[(32 + k) * 32 + lane];
            }
            g_hs[n * 32 + lane] = aS;
            g_hd[n * 32 + lane] = aD;
        }
        int gtid = nb * 256 + threadIdx.x;
        for (int i = gtid; i < N_NODES; i += ENC_NODE_BLOCKS * 256) g_hist[i] = 0;
    }
}

// ===== per-step: edge update — thread-per-edge, hoisted gathers, low-reg GEMV =====
__global__ void __launch_bounds__(128) edge_update(
        const float* __restrict__ eW, const float* __restrict__ eb,
        const float* __restrict__ lns, const float* __restrict__ lnb) {
    __shared__ float  sW[32 * 32];        // W rows 0..31, row-major [k*32+c]
    __shared__ float4 sprm[24];           // bias[0:8), scale[8:16), shift[16:24) as float4
    __shared__ float  sE[E_TILE * 36];    // 128 edge rows, stride 36 (quarter-warp conflict-free)

    int tid = threadIdx.x;
    for (int i = tid; i < 1024; i += 128) sW[i] = eW[i];
    if (tid < 8)       sprm[tid] = *(const float4*)&eb [tid * 4];
    else if (tid < 16) sprm[tid] = *(const float4*)&lns[(tid - 8) * 4];
    else if (tid < 24) sprm[tid] = *(const float4*)&lnb[(tid - 16) * 4];
    __syncthreads();

    for (int tile = blockIdx.x; tile < N_TILES; tile += gridDim.x) {
        int base = tile * E_TILE;
        int e = base + tid;

        // ---- hoisted: sender/receiver gathers + m init. These global loads are issued
        //      BEFORE the phase-1 tile load + barrier, so their L2 latency is covered.
        int2 sr = g_sr[e];
        float4 m[8];
#pragma unroll
        for (int c4 = 0; c4 < 8; c4++) {
            float4 hs4 = *(const float4*)&g_hs[sr.x * 32 + c4 * 4];
            float4 hd4 = *(const float4*)&g_hd[sr.y * 32 + c4 * 4];
            float4 b4  = sprm[c4];
            m[c4].x = b4.x + hs4.x + hd4.x;
            m[c4].y = b4.y + hs4.y + hd4.y;
            m[c4].z = b4.z + hs4.z + hd4.z;
            m[c4].w = b4.w + hs4.w + hd4.w;
        }

        // ---- phase 1: coalesced load of 128 e-rows into smem ----
        for (int j = tid; j < E_TILE * 8; j += 128) {
            int row = j >> 3, c4 = j & 7;
            *(float4*)&sE[row * 36 + c4 * 4] = *(const float4*)&g_e[(base + row) * 32 + c4 * 4];
        }
        __syncthreads();

        // ---- phase 2: GEMV; edge vector streamed from sE (no u[] register array) ----
#pragma unroll
        for (int k4 = 0; k4 < 8; k4++) {
            float4 uk = *(const float4*)&sE[tid * 36 + k4 * 4];   // own row, conflict-free
            float us[4] = {uk.x, uk.y, uk.z, uk.w};
#pragma unroll
            for (int kk = 0; kk < 4; kk++) {
                const float* wr = &sW[(k4 * 4 + kk) * 32];
                float s = us[kk];
#pragma unroll
                for (int c4 = 0; c4 < 8; c4++) {
                    float4 w4 = *(const float4*)&wr[c4 * 4];      // warp-broadcast
                    m[c4].x += s * w4.x;  m[c4].y += s * w4.y;
                    m[c4].z += s * w4.z;  m[c4].w += s * w4.w;
                }
            }
        }
        // leaky + LN stats (pure register math — no shuffles)
        float4 s4 = make_float4(0.f, 0.f, 0.f, 0.f);
        float4 q4 = make_float4(0.f, 0.f, 0.f, 0.f);
#pragma unroll
        for (int c4 = 0; c4 < 8; c4++) {
            m[c4].x = leaky(m[c4].x);  m[c4].y = leaky(m[c4].y);
            m[c4].z = leaky(m[c4].z);  m[c4].w = leaky(m[c4].w);
            s4.x += m[c4].x;  s4.y += m[c4].y;  s4.z += m[c4].z;  s4.w += m[c4].w;
            q4.x = fmaf(m[c4].x, m[c4].x, q4.x);
            q4.y = fmaf(m[c4].y, m[c4].y, q4.y);
            q4.z = fmaf(m[c4].z, m[c4].z, q4.z);
            q4.w = fmaf(m[c4].w, m[c4].w, q4.w);
        }
        float sm = (s4.x + s4.y) + (s4.z + s4.w);
        float qq = (q4.x + q4.y) + (q4.z + q4.w);
        float mu  = sm * (1.f / 32.f);
        float var = fmaxf(qq * (1.f / 32.f) - mu * mu, 0.f);
        float rs  = rsqrtf(var + LN_EPS);
        // epilogue: reload u per c4 from sE, write en back in place
#pragma unroll
        for (int c4 = 0; c4 < 8; c4++) {
            float4 u4  = *(const float4*)&sE[tid * 36 + c4 * 4];
            float4 sc4 = sprm[8 + c4], bi4 = sprm[16 + c4];
            float4 en;
            en.x = u4.x + (m[c4].x - mu) * rs * sc4.x + bi4.x;
            en.y = u4.y + (m[c4].y - mu) * rs * sc4.y + bi4.y;
            en.z = u4.z + (m[c4].z - mu) * rs * sc4.z + bi4.z;
            en.w = u4.w + (m[c4].w - mu) * rs * sc4.w + bi4.w;
            *(float4*)&sE[tid * 36 + c4 * 4] = en;
        }
        __syncthreads();

        // ---- phase 3: coalesced store ----
        for (int j = tid; j < E_TILE * 8; j += 128) {
            int row = j >> 3, c4 = j & 7;
            *(float4*)&g_e[(base + row) * 32 + c4 * 4] = *(const float4*)&sE[row * 36 + c4 * 4];
        }
        __syncthreads();
    }
}

// ================= per-step: node update (CSR gather) + next-step Hs/Hd or decoder ====
__global__ void __launch_bounds__(256) node_update(
        const float* __restrict__ nW, const float* __restrict__ nb,
        const float* __restrict__ lns, const float* __restrict__ lnb,
        const float* __restrict__ eW_next, int last,
        const float* __restrict__ dW1, const float* __restrict__ db1,
        const float* __restrict__ dW2, const float* __restrict__ db2,
        float* __restrict__ out) {
    __shared__ float wsT [32 * 68];   // node W transposed: wsT[c*68 + k], k in [0,64)
    __shared__ float ws2T[32 * 68];   // next-step eW rows 32..95 transposed (or dec_W1)
    __shared__ float sv  [8 * 64];    // per-warp staging: [0:32) av, [32:64) hn
    __shared__ float prm [96];

    for (int i = threadIdx.x; i < 2048; i += 256) {
        int k = i >> 5, c = i & 31;
        wsT[c * 68 + k] = nW[i];
        if (last) { if (i < 1024) ws2T[c * 68 + k] = dW1[i]; }
        else        ws2T[c * 68 + k] = eW_next[32 * 32 + i];
    }
    if (threadIdx.x < 32) {
        prm[threadIdx.x]      = nb[threadIdx.x];
        prm[32 + threadIdx.x] = lns[threadIdx.x];
        prm[64 + threadIdx.x] = lnb[threadIdx.x];
    }
    __syncthreads();
    int lane = threadIdx.x & 31;
    int wslot = (threadIdx.x >> 5) * 64;
    int warp = (blockIdx.x * blockDim.x + threadIdx.x) >> 5;
    int nwarps = (gridDim.x * blockDim.x) >> 5;
    float bias = prm[lane], sc = prm[32 + lane], bi = prm[64 + lane];

    for (int n = warp; n < N_NODES; n += nwarps) {
        int beg = g_off[n], end = g_off[n + 1];
        float s0 = 0.f, s1 = 0.f, s2 = 0.f, s3 = 0.f;
        int j = beg;
        for (; j + 3 < end; j += 4) {
            s0 += g_e[(j + 0) * 32 + lane];
            s1 += g_e[(j + 1) * 32 + lane];
            s2 += g_e[(j + 2) * 32 + lane];
            s3 += g_e[(j + 3) * 32 + lane];
        }
        for (; j < end; j++) s0 += g_e[j * 32 + lane];
        float av = ((s0 + s1) + (s2 + s3)) * g_inv[n];
        float hv = g_h[n * 32 + lane];       // brings row into L1
        sv[wslot + lane] = av;
        __syncwarp();

        float acc = bias, acb = 0.f;
#pragma unroll
        for (int k4 = 0; k4 < 8; k4++) {
            float4 hb = *(const float4*)&g_h[n * 32 + k4 * 4];   // uniform broadcast, L1-hit
            float4 ab = *(const float4*)&sv[wslot + k4 * 4];     // broadcast LDS.128
            const float* wr = &wsT[lane * 68 + k4 * 4];
            float4 w1 = *(const float4*)wr;
            float4 w2 = *(const float4*)(wr + 32);
            acc += hb.x * w1.x + ab.x * w2.x;
            acb += hb.y * w1.y + ab.y * w2.y;
            acc += hb.z * w1.z + ab.z * w2.z;
            acb += hb.w * w1.w + ab.w * w2.w;
        }
        float m = leaky(acc + acb);
        float sm = m, qq = m * m;
#pragma unroll
        for (int d = 16; d; d >>= 1) {
            sm += __shfl_xor_sync(0xffffffffu, sm, d);
            qq += __shfl_xor_sync(0xffffffffu, qq, d);
        }
        float mu = sm * (1.f / 32.f);
        float var = fmaxf(qq * (1.f / 32.f) - mu * mu, 0.f);
        float hn = hv + (m - mu) * rsqrtf(var + LN_EPS) * sc + bi;
        g_h[n * 32 + lane] = hn;
        sv[wslot + 32 + lane] = hn;
        __syncwarp();

        if (!last) {
            float aS = 0.f, aD = 0.f;
#pragma unroll
            for (int k4 = 0; k4 < 8; k4++) {
                float4 hb = *(const float4*)&sv[wslot + 32 + k4 * 4];
                const float* wr = &ws2T[lane * 68 + k4 * 4];
                float4 w1 = *(const float4*)wr;
                float4 w2 = *(const float4*)(wr + 32);
                aS += hb.x * w1.x; aD += hb.x * w2.x;
                aS += hb.y * w1.y; aD += hb.y * w2.y;
                aS += hb.z * w1.z; aD += hb.z * w2.z;
                aS += hb.w * w1.w; aD += hb.w * w2.w;
            }
            g_hs[n * 32 + lane] = aS;
            g_hd[n * 32 + lane] = aD;
        } else {
            float t = db1[lane];
#pragma unroll
            for (int k4 = 0; k4 < 8; k4++) {
                float4 hb = *(const float4*)&sv[wslot + 32 + k4 * 4];
                float4 w1 = *(const float4*)&ws2T[lane * 68 + k4 * 4];
                t += hb.x * w1.x + hb.y * w1.y + hb.z * w1.z + hb.w * w1.w;
            }
            t = leaky(t) * dW2[lane];
#pragma unroll
            for (int d = 16; d; d >>= 1)
                t += __shfl_xor_sync(0xffffffffu, t, d);
            if (lane == 0) out[n] = t + db2[0];
        }
        __syncwarp();
    }
}

// ================= launch =================
extern "C" void kernel_launch(void* const* d_in, const int* in_sizes, int n_in,
                              void* d_out, int out_size) {
    const float* x   = (const float*)d_in[0];
    const float* ea  = (const float*)d_in[1];
    const int*   snd = (const int*)d_in[2];
    const int*   rcv = (const int*)d_in[3];
    const float* neW = (const float*)d_in[4];
    const float* neb = (const float*)d_in[5];
    const float* eeW = (const float*)d_in[6];
    const float* eeb = (const float*)d_in[7];
    const float* eW  = (const float*)d_in[8];
    const float* eb  = (const float*)d_in[9];
    const float* els = (const float*)d_in[10];
    const float* elb = (const float*)d_in[11];
    const float* nW  = (const float*)d_in[12];
    const float* nb  = (const float*)d_in[13];
    const float* nls = (const float*)d_in[14];
    const float* nlb = (const float*)d_in[15];
    const float* dW1 = (const float*)d_in[16];
    const float* db1 = (const float*)d_in[17];
    const float* dW2 = (const float*)d_in[18];
    const float* db2 = (const float*)d_in[19];
    float* out = (float*)d_out;

    hist_edges<<<(N_EDGES + 255) / 256, 256>>>(rcv);
    scan_chunks<<<N_CHUNKS, SCAN_CHUNK>>>();
    scan_sums<<<1, 64>>>();
    add_offsets<<<(N_NODES + 255) / 256, 256>>>();
    fused_encode<<<ENC_EDGE_BLOCKS + ENC_NODE_BLOCKS, 256>>>(
        ea, snd, rcv, eeW, eeb, x, neW, neb, eW);

    for (int s = 0; s < STEPS; s++) {
        int last = (s == STEPS - 1);
        edge_update<<<EDGE_BLOCKS, 128>>>(eW + s * 96 * 32, eb + s * 32,
                                          els + s * 32, elb + s * 32);
        node_update<<<NODE_BLOCKS, 256>>>(nW + s * 64 * 32, nb + s * 32,
                                          nls + s * 32, nlb + s * 32,
                                          eW + (s + 1 < STEPS ? (s + 1) * 96 * 32 : 0), last,
                                          dW1, db1, dW2, db2, out);
    }
}